// round 13
// baseline (speedup 1.0000x reference)
#include <cuda_runtime.h>

// BallPointQuery: B=4, N=16384, M=2048, radius 0.2, MAX_SAMPLES=64.
// Output float32 [B, M, 64] (harness maps the reference's int64 to f32):
// ascending in-ball point indices, padded with the first found index
// (N if none found). Indices <= 16384 are exactly representable in f32.

#define BQ_B 4
#define BQ_N 16384
#define BQ_M 2048
#define BQ_MAXS 64
#define BQ_R2 0.04f

__global__ __launch_bounds__(256) void ball_query_kernel(
    const float* __restrict__ pcs,        // [B, N, 3]
    const float* __restrict__ centroids,  // [B, M, 3]
    float* __restrict__ out)              // [B, M, MAXS] float32
{
    const int w = blockIdx.x * (blockDim.x >> 5) + (threadIdx.x >> 5);
    const int lane = threadIdx.x & 31;
    if (w >= BQ_B * BQ_M) return;

    const int b = w / BQ_M;

    const float* c = centroids + (size_t)w * 3;
    const float cx = c[0], cy = c[1], cz = c[2];
    const float c2 = cx * cx + cy * cy + cz * cz;

    const float* pb = pcs + (size_t)b * BQ_N * 3;
    float* o = out + (size_t)w * BQ_MAXS;

    int cnt = 0;
    int first_idx = BQ_N;  // reference yields N when no point is in the ball

    #pragma unroll 1
    for (int base = 0; base < BQ_N; base += 32) {
        const int i = base + lane;
        const float px = pb[i * 3 + 0];
        const float py = pb[i * 3 + 1];
        const float pz = pb[i * 3 + 2];
        // Match reference numerics: d2 = c2 + p2 - 2*dot
        const float p2  = px * px + py * py + pz * pz;
        const float dot = cx * px + cy * py + cz * pz;
        const float d2  = c2 + p2 - 2.0f * dot;

        const bool hit = (d2 <= BQ_R2);
        const unsigned mask = __ballot_sync(0xffffffffu, hit);
        if (mask) {
            if (cnt == 0) first_idx = base + (__ffs(mask) - 1);
            if (hit) {
                const int pos = cnt + __popc(mask & ((1u << lane) - 1u));
                if (pos < BQ_MAXS) o[pos] = (float)i;
            }
            cnt += __popc(mask);
            if (cnt >= BQ_MAXS) break;  // warp-uniform (cnt derived from ballot)
        }
    }

    if (cnt < BQ_MAXS) {
        const float fv = (float)first_idx;
        for (int j = cnt + lane; j < BQ_MAXS; j += 32) {
            o[j] = fv;
        }
    }
}

extern "C" void kernel_launch(void* const* d_in, const int* in_sizes, int n_in,
                              void* d_out, int out_size)
{
    const float* pcs       = (const float*)d_in[0];  // 196608 floats
    const float* centroids = (const float*)d_in[1];  // 24576 floats
    float* out             = (float*)d_out;          // 524288 float32

    const int total_warps = BQ_B * BQ_M;             // 8192 warps, 1 per centroid
    const int threads = 256;                          // 8 warps/block
    const int blocks = (total_warps * 32 + threads - 1) / threads;  // 1024

    ball_query_kernel<<<blocks, threads>>>(pcs, centroids, out);
}

// round 14
// speedup vs baseline: 1.6730x; 1.6730x over previous
#include <cuda_runtime.h>

// BallPointQuery: B=4, N=16384, M=2048, radius 0.2, MAX_SAMPLES=64.
// Output float32 [B, M, 64]: ascending in-ball point indices, padded with the
// first found index (N if none found).
// One warp per centroid; 4x-unrolled scan (128 points/iter) for MLP=12.

#define BQ_B 4
#define BQ_N 16384
#define BQ_M 2048
#define BQ_MAXS 64
#define BQ_R2 0.04f
#define BQ_UNROLL 4

__global__ __launch_bounds__(256) void ball_query_kernel(
    const float* __restrict__ pcs,        // [B, N, 3]
    const float* __restrict__ centroids,  // [B, M, 3]
    float* __restrict__ out)              // [B, M, MAXS] float32
{
    const int w = blockIdx.x * (blockDim.x >> 5) + (threadIdx.x >> 5);
    const int lane = threadIdx.x & 31;
    if (w >= BQ_B * BQ_M) return;

    const int b = w / BQ_M;

    const float* c = centroids + (size_t)w * 3;
    const float cx = c[0], cy = c[1], cz = c[2];
    const float c2 = cx * cx + cy * cy + cz * cz;

    const float* pb = pcs + (size_t)b * BQ_N * 3;
    float* o = out + (size_t)w * BQ_MAXS;

    int cnt = 0;
    int first_idx = BQ_N;  // reference yields N when no point is in the ball

    #pragma unroll 1
    for (int base = 0; base < BQ_N; base += 32 * BQ_UNROLL) {
        // Phase 1: issue all loads + distance math for 4 groups (12 independent
        // LDGs in flight -> hides L1/L2 latency).
        float d2v[BQ_UNROLL];
        #pragma unroll
        for (int g = 0; g < BQ_UNROLL; g++) {
            const int i = base + g * 32 + lane;
            const float px = pb[i * 3 + 0];
            const float py = pb[i * 3 + 1];
            const float pz = pb[i * 3 + 2];
            // Match reference numerics: d2 = c2 + p2 - 2*dot
            const float p2  = px * px + py * py + pz * pz;
            const float dot = cx * px + cy * py + cz * pz;
            d2v[g] = c2 + p2 - 2.0f * dot;
        }

        // Phase 2: ordered ballots preserve ascending index order.
        #pragma unroll
        for (int g = 0; g < BQ_UNROLL; g++) {
            const bool hit = (d2v[g] <= BQ_R2);
            const unsigned mask = __ballot_sync(0xffffffffu, hit);
            if (mask) {
                if (cnt == 0) first_idx = base + g * 32 + (__ffs(mask) - 1);
                if (hit) {
                    const int pos = cnt + __popc(mask & ((1u << lane) - 1u));
                    if (pos < BQ_MAXS) o[pos] = (float)(base + g * 32 + lane);
                }
                cnt += __popc(mask);
            }
        }

        if (cnt >= BQ_MAXS) break;  // warp-uniform (cnt derived from ballots)
    }

    if (cnt < BQ_MAXS) {
        const float fv = (float)first_idx;
        for (int j = cnt + lane; j < BQ_MAXS; j += 32) {
            o[j] = fv;
        }
    }
}

extern "C" void kernel_launch(void* const* d_in, const int* in_sizes, int n_in,
                              void* d_out, int out_size)
{
    const float* pcs       = (const float*)d_in[0];  // 196608 floats
    const float* centroids = (const float*)d_in[1];  // 24576 floats
    float* out             = (float*)d_out;          // 524288 float32

    const int total_warps = BQ_B * BQ_M;             // 8192 warps, 1 per centroid
    const int threads = 256;                          // 8 warps/block
    const int blocks = (total_warps * 32 + threads - 1) / threads;  // 1024

    ball_query_kernel<<<blocks, threads>>>(pcs, centroids, out);
}

// round 15
// speedup vs baseline: 2.3526x; 1.4062x over previous
#include <cuda_runtime.h>

// BallPointQuery: B=4, N=16384, M=2048, radius 0.2, MAX_SAMPLES=64.
// Output float32 [B, M, 64]: ascending in-ball point indices, padded with the
// first found index (N if none found).
//
// Two kernels:
//  1. repack: (x,y,z) -> float4(x,y,z,p2) in __device__ scratch (1 MB)
//  2. ball query: one warp per centroid, 8x-unrolled scan; per point:
//     1 LDG.128 + 4 FMA instead of 3 LDG.32 + 6 FMA.

#define BQ_B 4
#define BQ_N 16384
#define BQ_M 2048
#define BQ_MAXS 64
#define BQ_R2 0.04f
#define BQ_UNROLL 8

__device__ float4 g_pts[BQ_B * BQ_N];   // 1 MB scratch (sanctioned __device__ global)

__global__ __launch_bounds__(256) void repack_kernel(const float* __restrict__ pcs)
{
    const int i = blockIdx.x * blockDim.x + threadIdx.x;
    if (i < BQ_B * BQ_N) {
        const float px = pcs[i * 3 + 0];
        const float py = pcs[i * 3 + 1];
        const float pz = pcs[i * 3 + 2];
        const float p2 = px * px + py * py + pz * pz;  // same expr as before
        g_pts[i] = make_float4(px, py, pz, p2);
    }
}

__global__ __launch_bounds__(256, 4) void ball_query_kernel(
    const float* __restrict__ centroids,  // [B, M, 3]
    float* __restrict__ out)              // [B, M, MAXS] float32
{
    const int w = blockIdx.x * (blockDim.x >> 5) + (threadIdx.x >> 5);
    const int lane = threadIdx.x & 31;
    if (w >= BQ_B * BQ_M) return;

    const int b = w / BQ_M;

    const float* c = centroids + (size_t)w * 3;
    const float cx = c[0], cy = c[1], cz = c[2];
    const float c2 = cx * cx + cy * cy + cz * cz;

    const float4* __restrict__ pb = g_pts + (size_t)b * BQ_N;
    float* o = out + (size_t)w * BQ_MAXS;

    int cnt = 0;
    int first_idx = BQ_N;  // reference yields N when no point is in the ball

    #pragma unroll 1
    for (int base = 0; base < BQ_N; base += 32 * BQ_UNROLL) {
        // Phase 1: 8 independent LDG.128 in flight, then the distance math.
        float d2v[BQ_UNROLL];
        #pragma unroll
        for (int g = 0; g < BQ_UNROLL; g++) {
            const float4 p = pb[base + g * 32 + lane];
            const float dot = cx * p.x + cy * p.y + cz * p.z;
            d2v[g] = c2 + p.w - 2.0f * dot;   // same numeric form as R13/R14
        }

        // Phase 2: ordered ballots preserve ascending index order.
        #pragma unroll
        for (int g = 0; g < BQ_UNROLL; g++) {
            const bool hit = (d2v[g] <= BQ_R2);
            const unsigned mask = __ballot_sync(0xffffffffu, hit);
            if (mask) {
                if (cnt == 0) first_idx = base + g * 32 + (__ffs(mask) - 1);
                if (hit) {
                    const int pos = cnt + __popc(mask & ((1u << lane) - 1u));
                    if (pos < BQ_MAXS) o[pos] = (float)(base + g * 32 + lane);
                }
                cnt += __popc(mask);
            }
        }

        if (cnt >= BQ_MAXS) break;  // warp-uniform (cnt derived from ballots)
    }

    if (cnt < BQ_MAXS) {
        const float fv = (float)first_idx;
        for (int j = cnt + lane; j < BQ_MAXS; j += 32) {
            o[j] = fv;
        }
    }
}

extern "C" void kernel_launch(void* const* d_in, const int* in_sizes, int n_in,
                              void* d_out, int out_size)
{
    const float* pcs       = (const float*)d_in[0];  // 196608 floats
    const float* centroids = (const float*)d_in[1];  // 24576 floats
    float* out             = (float*)d_out;          // 524288 float32

    // Repack points: (x,y,z) -> (x,y,z,p2)
    const int npts = BQ_B * BQ_N;                    // 65536
    repack_kernel<<<(npts + 255) / 256, 256>>>(pcs);

    // Main query: one warp per centroid
    const int total_warps = BQ_B * BQ_M;             // 8192
    const int threads = 256;                          // 8 warps/block
    const int blocks = (total_warps * 32 + threads - 1) / threads;  // 1024
    ball_query_kernel<<<blocks, threads>>>(centroids, out);
}